// round 5
// baseline (speedup 1.0000x reference)
#include <cuda_runtime.h>
#include <cstdint>

#define BATCH   32
#define SEQLEN  4096
#define CIN     7
#define OUTC    512
#define NKERN   74
#define TB      64                   // timesteps per block (smaller tile -> 6.9 waves, tiny tail)
#define NT      256                  // threads per block (1 output pair each)
#define T       16                   // output timesteps per accumulator chunk
#define SROWS   (TB + 24)            // smem rows: t0-22 .. t0+TB+1
#define NCOMBO  11                   // distinct (cA,cB) channel pairs

// ---------- packed f32x2 helpers ----------
__device__ __forceinline__ unsigned long long pack2(float lo, float hi) {
    unsigned long long r;
    asm("mov.b64 %0, {%1, %2};" : "=l"(r) : "f"(lo), "f"(hi));
    return r;
}
__device__ __forceinline__ void fma2(unsigned long long& acc,
                                     unsigned long long a, unsigned long long b) {
    asm("fma.rn.f32x2 %0, %1, %2, %0;" : "+l"(acc) : "l"(a), "l"(b));
}

// Dense 24-tap FIR: out[b,t,o] = sum_{d=0}^{23} W[o,d] * x[b, t+d-22, c(o)]
// tap d (offset o = d-22) maps to kernel (i,j): i = (1-o)/3, j = o+1+3i.

__global__ __launch_bounds__(NT, 2)
void conv_main(const float* __restrict__ x, const float* __restrict__ kern,
               float* __restrict__ out) {
    __shared__ float  xs[CIN][SROWS];
    __shared__ float2 pk[NCOMBO][SROWS];     // packed (xA, xB) per channel-combo
    __shared__ float  ks[NKERN * 24];

    const int nt_tiles = SEQLEN / TB;        // 64
    const int b   = blockIdx.x / nt_tiles;
    const int t0  = (blockIdx.x % nt_tiles) * TB;
    const int tid = threadIdx.x;

    // ---- phase 1: raw x window + kernel weights into smem ----
    {
        const float* xb = x + (size_t)b * SEQLEN * CIN;
        for (int idx = tid; idx < CIN * SROWS; idx += NT) {
            int r = idx / CIN;
            int c = idx % CIN;
            int g = t0 - 22 + r;
            float v = 0.0f;
            if (g >= 0 && g < SEQLEN) v = xb[(size_t)g * CIN + c];
            xs[c][r] = v;
        }
        for (int idx = tid; idx < NKERN * 24; idx += NT)
            ks[idx] = kern[idx];
    }
    __syncthreads();

    // ---- phase 2: build packed channel-pair arrays ----
    // combos 0..6: (c,c); 7:(0,1) 8:(2,3) 9:(4,5) 10:(6,0)
    for (int idx = tid; idx < NCOMBO * SROWS; idx += NT) {
        int cm = idx / SROWS, r = idx % SROWS;
        int ca, cb;
        if (cm < 7)       { ca = cm;           cb = cm; }
        else if (cm < 10) { ca = 2 * (cm - 7); cb = ca + 1; }
        else              { ca = 6;            cb = 0; }
        pk[cm][r] = make_float2(xs[ca][r], xs[cb][r]);
    }
    __syncthreads();

    // ---- this thread's output pair (o0 even -> aligned STG.64) ----
    const int o0 = 2 * tid;
    const int o1 = o0 + 1;
    const int cA = o0 / 73, kA = o0 % 73;
    int cB, kB;
    if (o1 == 511) { cB = 0; kB = 73; } else { cB = o1 / 73; kB = o1 % 73; }

    int combo;
    if (cA == cB)        combo = cA;
    else if (o1 == 511)  combo = 10;
    else                 combo = 7 + (cA >> 1);

    // ---- packed weight pairs in registers (48 regs) ----
    unsigned long long wreg[24];
#pragma unroll
    for (int d = 0; d < 24; d++) {
        const int o = d - 22;
        const int i = (1 - o) / 3;
        const int j = o + 1 + 3 * i;
        wreg[d] = pack2(ks[kA * 24 + i * 3 + j], ks[kB * 24 + i * 3 + j]);
    }

    const unsigned long long* pkc =
        reinterpret_cast<const unsigned long long*>(pk[combo]);
    float* op = out + ((size_t)b * SEQLEN + t0) * OUTC + o0;

    // ---- streaming-accumulator FIR with IN-LOOP stores ----
    // acc[tr] is complete once gg == tr + 23; store it right there so STG.64s
    // are spaced ~24 FMA2s apart instead of bursting 16 deep at chunk end.
#pragma unroll 1
    for (int cbase = 0; cbase < TB; cbase += T) {
        unsigned long long acc[T];
#pragma unroll
        for (int tr = 0; tr < T; tr++) acc[tr] = 0ull;

#pragma unroll
        for (int gg = 0; gg < T + 23; gg++) {
            const unsigned long long px = pkc[cbase + gg];   // one LDS.64 (broadcast)
#pragma unroll
            for (int tr = 0; tr < T; tr++) {
                const int d = gg - tr;                        // compile-time
                if (d >= 0 && d < 24) fma2(acc[tr], px, wreg[d]);
            }
            if (gg >= 23) {                                   // compile-time branch
                const int tr = gg - 23;
                *reinterpret_cast<unsigned long long*>(
                    op + (size_t)(cbase + tr) * OUTC) = acc[tr];
            }
        }
    }

    // ---- folded t = L-1 fix: right padding kills ALL j==2 taps there ----
    // Same thread re-stores its own pair -> program-ordered WAW, safe.
    if (t0 + TB == SEQLEN) {
        const int row = TB + 21;                  // local row of t = L-1
        float sA = 0.0f, sB = 0.0f;
#pragma unroll
        for (int i = 0; i < 8; i++) {
#pragma unroll
            for (int j = 0; j < 2; j++) {
                const int r = row + (j - 1) - 3 * i;
                const float2 v = pk[combo][r];
                sA += v.x * ks[kA * 24 + i * 3 + j];
                sB += v.y * ks[kB * 24 + i * 3 + j];
            }
        }
        *reinterpret_cast<unsigned long long*>(
            out + ((size_t)b * SEQLEN + (SEQLEN - 1)) * OUTC + o0) = pack2(sA, sB);
    }
}

extern "C" void kernel_launch(void* const* d_in, const int* in_sizes, int n_in,
                              void* d_out, int out_size) {
    const float* x    = (const float*)d_in[0];   // (32, 4096, 7) f32
    const float* kern = (const float*)d_in[1];   // (74, 8, 3)  f32
    float* out        = (float*)d_out;           // (32, 4096, 512) f32

    conv_main<<<BATCH * (SEQLEN / TB), NT>>>(x, kern, out);
}

// round 6
// speedup vs baseline: 1.1615x; 1.1615x over previous
#include <cuda_runtime.h>
#include <cstdint>

#define BATCH   32
#define SEQLEN  4096
#define CIN     7
#define OUTC    512
#define NKERN   74
#define TB      128                  // timesteps per block
#define NT      256                  // threads per block (1 output pair each)
#define T       16                   // output timesteps per accumulator chunk
#define SROWS   (TB + 24)            // smem rows: t0-22 .. t0+TB+1  (152, even)
#define NCOMBO  11                   // distinct (cA,cB) channel pairs

// ---------- packed f32x2 helpers ----------
__device__ __forceinline__ unsigned long long pack2(float lo, float hi) {
    unsigned long long r;
    asm("mov.b64 %0, {%1, %2};" : "=l"(r) : "f"(lo), "f"(hi));
    return r;
}
__device__ __forceinline__ void fma2(unsigned long long& acc,
                                     unsigned long long a, unsigned long long b) {
    asm("fma.rn.f32x2 %0, %1, %2, %0;" : "+l"(acc) : "l"(a), "l"(b));
}

// Dense 24-tap FIR: out[b,t,o] = sum_{d=0}^{23} W[o,d] * x[b, t+d-22, c(o)]
// tap d (offset o = d-22) maps to kernel (i,j): i = (1-o)/3, j = o+1+3i.

__global__ __launch_bounds__(NT, 2)
void conv_main(const float* __restrict__ x, const float* __restrict__ kern,
               float* __restrict__ out) {
    __shared__ float xs[CIN][SROWS];
    __shared__ __align__(16) float2 pk[NCOMBO][SROWS];   // packed (xA,xB) per combo
    __shared__ float ks[NKERN * 24];

    const int nt_tiles = SEQLEN / TB;        // 32
    const int b   = blockIdx.x / nt_tiles;
    const int t0  = (blockIdx.x % nt_tiles) * TB;
    const int tid = threadIdx.x;

    // ---- phase 1: raw x window + kernel weights into smem ----
    {
        const float* xb = x + (size_t)b * SEQLEN * CIN;
        for (int idx = tid; idx < CIN * SROWS; idx += NT) {
            int r = idx / CIN;
            int c = idx % CIN;
            int g = t0 - 22 + r;
            float v = 0.0f;
            if (g >= 0 && g < SEQLEN) v = xb[(size_t)g * CIN + c];
            xs[c][r] = v;
        }
        for (int idx = tid; idx < NKERN * 24; idx += NT)
            ks[idx] = kern[idx];
    }
    __syncthreads();

    // ---- phase 2: build packed channel-pair arrays ----
    // combos 0..6: (c,c); 7:(0,1) 8:(2,3) 9:(4,5) 10:(6,0)
    for (int idx = tid; idx < NCOMBO * SROWS; idx += NT) {
        int cm = idx / SROWS, r = idx % SROWS;
        int ca, cb;
        if (cm < 7)       { ca = cm;           cb = cm; }
        else if (cm < 10) { ca = 2 * (cm - 7); cb = ca + 1; }
        else              { ca = 6;            cb = 0; }
        pk[cm][r] = make_float2(xs[ca][r], xs[cb][r]);
    }
    __syncthreads();

    // ---- this thread's output pair (o0 even -> aligned STG.64) ----
    const int o0 = 2 * tid;
    const int o1 = o0 + 1;
    const int cA = o0 / 73, kA = o0 % 73;
    int cB, kB;
    if (o1 == 511) { cB = 0; kB = 73; } else { cB = o1 / 73; kB = o1 % 73; }

    int combo;
    if (cA == cB)        combo = cA;
    else if (o1 == 511)  combo = 10;
    else                 combo = 7 + (cA >> 1);

    // ---- packed weight pairs in registers (48 regs) ----
    unsigned long long wreg[24];
#pragma unroll
    for (int d = 0; d < 24; d++) {
        const int o = d - 22;
        const int i = (1 - o) / 3;
        const int j = o + 1 + 3 * i;
        wreg[d] = pack2(ks[kA * 24 + i * 3 + j], ks[kB * 24 + i * 3 + j]);
    }

    // float4 view: element q holds packed rows (2q, 2q+1) of this combo stream
    const float4* pk4 = reinterpret_cast<const float4*>(pk[combo]);
    float* op = out + ((size_t)b * SEQLEN + t0) * OUTC + o0;

    // ---- streaming-accumulator FIR: T=16 outputs per chunk, LDS.128 per 2 rows ----
#pragma unroll 1
    for (int cbase = 0; cbase < TB; cbase += T) {
        unsigned long long acc[T];
#pragma unroll
        for (int tr = 0; tr < T; tr++) acc[tr] = 0ull;

#pragma unroll
        for (int gp = 0; gp < (T + 24) / 2; gp++) {          // 20 pairs: rows gg, gg+1
            const float4 q = pk4[(cbase >> 1) + gp];          // one LDS.128 (broadcast)
            const unsigned long long px0 = pack2(q.x, q.y);   // row 2*gp
            const unsigned long long px1 = pack2(q.z, q.w);   // row 2*gp+1
            const int gg = 2 * gp;
#pragma unroll
            for (int tr = 0; tr < T; tr++) {
                const int d0 = gg - tr;                       // compile-time
                if (d0 >= 0 && d0 < 24) fma2(acc[tr], px0, wreg[d0]);
                const int d1 = gg + 1 - tr;
                if (d1 >= 0 && d1 < 24) fma2(acc[tr], px1, wreg[d1]);
            }
        }

#pragma unroll
        for (int tr = 0; tr < T; tr++)
            *reinterpret_cast<unsigned long long*>(op + (size_t)tr * OUTC) = acc[tr];
        op += (size_t)T * OUTC;
    }

    // ---- folded t = L-1 fix: right padding kills ALL j==2 taps there ----
    // Same thread re-stores its own pair -> program-ordered WAW, safe.
    if (t0 + TB == SEQLEN) {
        const int row = TB + 21;                  // local row of t = L-1
        float sA = 0.0f, sB = 0.0f;
#pragma unroll
        for (int i = 0; i < 8; i++) {
#pragma unroll
            for (int j = 0; j < 2; j++) {
                const int r = row + (j - 1) - 3 * i;
                const float2 v = pk[combo][r];
                sA += v.x * ks[kA * 24 + i * 3 + j];
                sB += v.y * ks[kB * 24 + i * 3 + j];
            }
        }
        *reinterpret_cast<unsigned long long*>(
            out + ((size_t)b * SEQLEN + (SEQLEN - 1)) * OUTC + o0) = pack2(sA, sB);
    }
}

extern "C" void kernel_launch(void* const* d_in, const int* in_sizes, int n_in,
                              void* d_out, int out_size) {
    const float* x    = (const float*)d_in[0];   // (32, 4096, 7) f32
    const float* kern = (const float*)d_in[1];   // (74, 8, 3)  f32
    float* out        = (float*)d_out;           // (32, 4096, 512) f32

    conv_main<<<BATCH * (SEQLEN / TB), NT>>>(x, kern, out);
}